// round 9
// baseline (speedup 1.0000x reference)
#include <cuda_runtime.h>
#include <math.h>

// Problem constants (fixed shapes per reference)
#define NFK 4096
#define NRK 8192
#define NTH 256
#define NT 4                    // r rows per thread (2 packed pairs)
#define RBLK (NTH*NT)           // 1024 r per tile
#define FCHUNK 128              // f columns per tile
#define NCH (NFK/FCHUNK)        // 32 f-chunks
#define NRB (NRK/RBLK)          // 8 r-blocks
#define NTILES (NCH*NRB)        // 256 tiles == grid size

#define EPS_CH   1e-5f
#define EPS_ACOS 1e-6f
#define PI_F     3.14159265358979323846f

// ---------------- static device scratch (allocation-free) ----------------
// All reduction scratch has reset value 0 ("no update"): zero-init on run 1,
// and the elected last block writes 0 back after consuming, re-arming each
// replay. g_done is monotonic, used mod NTILES (exactly NTILES increments per
// run -> exactly one elected block per run). No block ever waits on another.
__device__ unsigned g_done;            // finisher election counter
__device__ unsigned g_ru[NRK];         // max of ~ford(u)  -> min over f of u
__device__ unsigned g_rtr[NRK];        // max of  ford(tr) -> max over f of tr
__device__ unsigned g_fv[NFK];         // max of ~ford(v)  -> min over r of v
__device__ unsigned g_ftr[NFK];        // max of  ford(tr) -> max over r of tr

// Order-preserving float<->uint mapping (min/max in integer domain).
__device__ __forceinline__ unsigned ford(float f) {
    unsigned u = __float_as_uint(f);
    return (u & 0x80000000u) ? ~u : (u | 0x80000000u);
}
__device__ __forceinline__ float finv(unsigned u) {
    return __uint_as_float((u & 0x80000000u) ? (u & 0x7fffffffu) : ~u);
}

// ---------------- packed f32x2 helpers ----------------
__device__ __forceinline__ unsigned long long pk2(float a, float b) {
    unsigned long long r;
    asm("mov.b64 %0, {%1, %2};" : "=l"(r) : "f"(a), "f"(b));
    return r;
}
__device__ __forceinline__ unsigned long long ffma2(unsigned long long a,
                                                    unsigned long long b,
                                                    unsigned long long c) {
    unsigned long long d;
    asm("fma.rn.f32x2 %0, %1, %2, %3;" : "=l"(d) : "l"(a), "l"(b), "l"(c));
    return d;
}
__device__ __forceinline__ unsigned long long fmul2(unsigned long long a,
                                                    unsigned long long b) {
    unsigned long long d;
    asm("mul.rn.f32x2 %0, %1, %2;" : "=l"(d) : "l"(a), "l"(b));
    return d;
}
__device__ __forceinline__ float f2lo(unsigned long long v) {
    return __uint_as_float((unsigned)v);
}
__device__ __forceinline__ float f2hi(unsigned long long v) {
    return __uint_as_float((unsigned)(v >> 32));
}

// ---------------- fused kernel: tiles + last-block epilogue ----------------
__global__ __launch_bounds__(NTH, 2)
void fused_kernel(const float* __restrict__ t_fake,
                  const float* __restrict__ R_fake,
                  const float* __restrict__ r_buffer,
                  const float* __restrict__ t_buffer,
                  float* __restrict__ out) {
    __shared__ __align__(16) float sf[FCHUNK * 28];          // 14 KB f-tile
    __shared__ __align__(16) uint2 s_fred[FCHUNK][8];        // 8 KB per-warp f results
    __shared__ int s_fin;
    __shared__ float s_buf[NTH/32][4];

    const int tid  = threadIdx.x;
    const int lane = tid & 31;
    const int warp = tid >> 5;

    const int cx = blockIdx.x & (NCH - 1);
    const int ry = blockIdx.x >> 5;
    const int fbase = cx * FCHUNK;
    const int rbase = ry * RBLK;

    // ======== phase 1: all-pairs tile (identical to R7 pair kernel) ========
    for (int i = tid; i < FCHUNK * 12; i += NTH) {
        int fl = i / 12, v = i - fl * 12;
        int fg = fbase + fl;
        float val = (v < 3) ? t_fake[fg * 3 + v] : R_fake[fg * 9 + (v - 3)];
        int slot = (v < 3) ? v : (v + 1);
        sf[fl * 28 + slot * 2 + 0] = val;
        sf[fl * 28 + slot * 2 + 1] = val;
    }
    for (int fl = tid; fl < FCHUNK; fl += NTH) {
        int fg = fbase + fl;
        float tx = t_fake[fg*3+0], ty = t_fake[fg*3+1], tz = t_fake[fg*3+2];
        float nf = fmaf(tx, tx, fmaf(ty, ty, tz * tz));
        sf[fl * 28 + 6] = nf;
        sf[fl * 28 + 7] = nf;
    }

    const int r0 = rbase + tid * NT;
    unsigned long long tb2[2][3], Rr2[2][9], nr2[2];
    #pragma unroll
    for (int jp = 0; jp < 2; jp++) {
        int ra = r0 + 2 * jp, rb = ra + 1;
        float ax = t_buffer[ra*3+0], ay = t_buffer[ra*3+1], az = t_buffer[ra*3+2];
        float bx = t_buffer[rb*3+0], by = t_buffer[rb*3+1], bz = t_buffer[rb*3+2];
        tb2[jp][0] = pk2(ax, bx);
        tb2[jp][1] = pk2(ay, by);
        tb2[jp][2] = pk2(az, bz);
        nr2[jp] = pk2(fmaf(ax, ax, fmaf(ay, ay, az * az)),
                      fmaf(bx, bx, fmaf(by, by, bz * bz)));
        #pragma unroll
        for (int k = 0; k < 9; k++)
            Rr2[jp][k] = pk2(r_buffer[ra*9+k], r_buffer[rb*9+k]);
    }
    __syncthreads();

    const float INF = __int_as_float(0x7f800000);
    const unsigned long long M2 = pk2(-2.0f, -2.0f);
    float minu[NT], maxtr[NT];
    #pragma unroll
    for (int j = 0; j < NT; j++) { minu[j] = INF; maxtr[j] = -INF; }

    #pragma unroll 2
    for (int f = 0; f < FCHUNK; f++) {
        const ulonglong2* fp = reinterpret_cast<const ulonglong2*>(sf + f * 28);
        ulonglong2 A = fp[0];   // tx2, ty2
        ulonglong2 B = fp[1];   // tz2, nf2
        ulonglong2 C = fp[2];   // R0, R1
        ulonglong2 D = fp[3];   // R2, R3
        ulonglong2 E = fp[4];   // R4, R5
        ulonglong2 F = fp[5];   // R6, R7
        ulonglong2 G = fp[6];   // R8, pad

        unsigned long long v2s[2], trs[2];
        #pragma unroll
        for (int jp = 0; jp < 2; jp++) {
            unsigned long long dot =
                ffma2(tb2[jp][0], A.x, ffma2(tb2[jp][1], A.y, fmul2(tb2[jp][2], B.x)));
            unsigned long long u2 = ffma2(dot, M2, B.y);       // nf - 2 dot
            v2s[jp] = ffma2(dot, M2, nr2[jp]);                 // nr - 2 dot
            unsigned long long tr = fmul2(Rr2[jp][0], C.x);
            tr = ffma2(Rr2[jp][1], C.y, tr);
            tr = ffma2(Rr2[jp][2], D.x, tr);
            tr = ffma2(Rr2[jp][3], D.y, tr);
            tr = ffma2(Rr2[jp][4], E.x, tr);
            tr = ffma2(Rr2[jp][5], E.y, tr);
            tr = ffma2(Rr2[jp][6], F.x, tr);
            tr = ffma2(Rr2[jp][7], F.y, tr);
            tr = ffma2(Rr2[jp][8], G.x, tr);
            trs[jp] = tr;

            minu[2*jp+0]  = fminf(minu[2*jp+0],  f2lo(u2));
            minu[2*jp+1]  = fminf(minu[2*jp+1],  f2hi(u2));
            maxtr[2*jp+0] = fmaxf(maxtr[2*jp+0], f2lo(tr));
            maxtr[2*jp+1] = fmaxf(maxtr[2*jp+1], f2hi(tr));
        }
        float fv = fminf(fminf(f2lo(v2s[0]), f2hi(v2s[0])),
                         fminf(f2lo(v2s[1]), f2hi(v2s[1])));
        float ft = fmaxf(fmaxf(f2lo(trs[0]), f2hi(trs[0])),
                         fmaxf(f2lo(trs[1]), f2hi(trs[1])));

        unsigned ev = __reduce_max_sync(0xffffffffu, ~ford(fv));
        unsigned et = __reduce_max_sync(0xffffffffu, ford(ft));
        if (lane == 0) s_fred[f][warp] = make_uint2(ev, et);
    }

    // per-r merge: fire-and-forget RED.MAX
    #pragma unroll
    for (int j = 0; j < NT; j++) {
        atomicMax(&g_ru[r0 + j],  ~ford(minu[j]));
        atomicMax(&g_rtr[r0 + j],  ford(maxtr[j]));
    }

    // block combine of per-warp f results, then RED.MAX (2 per f)
    __syncthreads();
    if (tid < FCHUNK) {
        const uint4* p = reinterpret_cast<const uint4*>(&s_fred[tid][0]);
        unsigned ev = 0u, et = 0u;
        #pragma unroll
        for (int k = 0; k < 4; k++) {
            uint4 q = p[k];
            ev = umax(ev, umax(q.x, q.z));
            et = umax(et, umax(q.y, q.w));
        }
        atomicMax(&g_fv[fbase + tid],  ev);
        atomicMax(&g_ftr[fbase + tid], et);
    }

    // ======== election: last block to finish runs the epilogue alone ========
    __threadfence();                                // publish all RED.MAX
    if (tid == 0) {
        unsigned old = atomicAdd(&g_done, 1u);
        s_fin = ((old & (NTILES - 1u)) == (NTILES - 1u));
    }
    __syncthreads();
    if (!s_fin) return;                             // non-elected blocks exit: no waiting

    __threadfence();                                // acquire all published updates

    // ======== phase 2 (elected block only): 12288 items over 256 threads ====
    float sAngR = 0.f, sSqR = 0.f, sAngF = 0.f, sSqF = 0.f;

    for (int i = tid; i < NRK; i += NTH) {
        unsigned eu = __ldcg(&g_ru[i]);             // L1-bypass: atomic-written
        unsigned et = __ldcg(&g_rtr[i]);
        g_ru[i] = 0u;                               // re-arm for next replay
        g_rtr[i] = 0u;
        float tx = t_buffer[i*3+0], ty = t_buffer[i*3+1], tz = t_buffer[i*3+2];
        float nr = fmaf(tx, tx, fmaf(ty, ty, tz * tz));
        float td = fmaxf(nr + finv(~eu), 0.0f);
        sSqR += sqrtf(td + EPS_CH);
        float cs = 0.5f * (finv(et) - 1.0f);
        cs = fminf(fmaxf(cs, -1.0f + EPS_ACOS), 1.0f - EPS_ACOS);
        sAngR += acosf(cs);
    }
    for (int i = tid; i < NFK; i += NTH) {
        unsigned ev = __ldcg(&g_fv[i]);
        unsigned et = __ldcg(&g_ftr[i]);
        g_fv[i] = 0u;
        g_ftr[i] = 0u;
        float tx = t_fake[i*3+0], ty = t_fake[i*3+1], tz = t_fake[i*3+2];
        float nf = fmaf(tx, tx, fmaf(ty, ty, tz * tz));
        float td = fmaxf(nf + finv(~ev), 0.0f);
        sSqF += sqrtf(td + EPS_CH);
        float cs = 0.5f * (finv(et) - 1.0f);
        cs = fminf(fmaxf(cs, -1.0f + EPS_ACOS), 1.0f - EPS_ACOS);
        sAngF += acosf(cs);
    }

    // fixed-tree block reduction (deterministic)
    #pragma unroll
    for (int off = 16; off; off >>= 1) {
        sAngR += __shfl_xor_sync(0xffffffffu, sAngR, off);
        sSqR  += __shfl_xor_sync(0xffffffffu, sSqR,  off);
        sAngF += __shfl_xor_sync(0xffffffffu, sAngF, off);
        sSqF  += __shfl_xor_sync(0xffffffffu, sSqF,  off);
    }
    if (lane == 0) {
        s_buf[warp][0] = sAngR; s_buf[warp][1] = sSqR;
        s_buf[warp][2] = sAngF; s_buf[warp][3] = sSqF;
    }
    __syncthreads();

    if (tid == 0) {
        float a0 = 0.f, a1 = 0.f, a2 = 0.f, a3 = 0.f;
        #pragma unroll
        for (int i = 0; i < NTH/32; i++) {
            a0 += s_buf[i][0]; a1 += s_buf[i][1]; a2 += s_buf[i][2]; a3 += s_buf[i][3];
        }
        float rloss = a2 / (float)NFK + a0 / (float)NRK;
        float tloss = a1 / (float)NRK + a3 / (float)NFK;
        out[0] = rloss + tloss * PI_F;
    }
}

// ---------------- launch: single kernel ----------------
extern "C" void kernel_launch(void* const* d_in, const int* in_sizes, int n_in,
                              void* d_out, int out_size) {
    const float* t_fake   = nullptr;  // 4096*3
    const float* R_fake   = nullptr;  // 4096*9
    const float* r_buffer = nullptr;  // 8192*9
    const float* t_buffer = nullptr;  // 8192*3
    for (int i = 0; i < n_in; i++) {
        switch (in_sizes[i]) {
            case NFK*3: t_fake   = (const float*)d_in[i]; break;
            case NFK*9: R_fake   = (const float*)d_in[i]; break;
            case NRK*9: r_buffer = (const float*)d_in[i]; break;
            case NRK*3: t_buffer = (const float*)d_in[i]; break;
            default: break;
        }
    }

    fused_kernel<<<NTILES, NTH>>>(t_fake, R_fake, r_buffer, t_buffer, (float*)d_out);
}

// round 11
// speedup vs baseline: 1.3194x; 1.3194x over previous
#include <cuda_runtime.h>
#include <math.h>

// Problem constants (fixed shapes per reference)
#define NFK 4096
#define NRK 8192
#define NTH 256
#define NT 2                    // r rows per thread (1 packed pair)
#define RBLK (NTH*NT)           // 512 r per tile
#define FCHUNK 128              // f columns per tile
#define NCH (NFK/FCHUNK)        // 32 f-chunks
#define NRB (NRK/RBLK)          // 16 r-blocks
#define NTILES (NCH*NRB)        // 512 tiles == grid size
#define EBLK 48                 // epilogue blocks: 48*256 = NRK+NFK exactly

#define EPS_CH   1e-5f
#define EPS_ACOS 1e-6f
#define PI_F     3.14159265358979323846f

// ---------------- static device scratch (allocation-free) ----------------
// All reduction scratch has reset value 0 ("no update"): zero-init on run 1,
// epilogue writes 0 back after consuming -> re-armed for every graph replay.
// g_done is monotonic, used mod EBLK (exactly EBLK increments per run).
__device__ unsigned g_done;            // finisher election counter
__device__ unsigned g_ru[NRK];         // max of ~ford(u)  -> min over f of u
__device__ unsigned g_rtr[NRK];        // max of  ford(tr) -> max over f of tr
__device__ unsigned g_fv[NFK];         // max of ~ford(v)  -> min over r of v
__device__ unsigned g_ftr[NFK];        // max of  ford(tr) -> max over r of tr
__device__ float    g_psum[4][EBLK];   // SoA per-epilogue-block partial sums

// Order-preserving float<->uint mapping (min/max in integer domain).
__device__ __forceinline__ unsigned ford(float f) {
    unsigned u = __float_as_uint(f);
    return (u & 0x80000000u) ? ~u : (u | 0x80000000u);
}
__device__ __forceinline__ float finv(unsigned u) {
    return __uint_as_float((u & 0x80000000u) ? (u & 0x7fffffffu) : ~u);
}

// ---------------- packed f32x2 helpers ----------------
__device__ __forceinline__ unsigned long long pk2(float a, float b) {
    unsigned long long r;
    asm("mov.b64 %0, {%1, %2};" : "=l"(r) : "f"(a), "f"(b));
    return r;
}
// register-pair extraction: resolves to register aliasing, no SHF
__device__ __forceinline__ void unpk2(unsigned long long v, float& lo, float& hi) {
    asm("mov.b64 {%0, %1}, %2;" : "=f"(lo), "=f"(hi) : "l"(v));
}
__device__ __forceinline__ unsigned long long ffma2(unsigned long long a,
                                                    unsigned long long b,
                                                    unsigned long long c) {
    unsigned long long d;
    asm("fma.rn.f32x2 %0, %1, %2, %3;" : "=l"(d) : "l"(a), "l"(b), "l"(c));
    return d;
}
__device__ __forceinline__ unsigned long long fmul2(unsigned long long a,
                                                    unsigned long long b) {
    unsigned long long d;
    asm("mul.rn.f32x2 %0, %1, %2;" : "=l"(d) : "l"(a), "l"(b));
    return d;
}

// ---------------- all-pairs kernel: one tile per block, occ 3 ----------------
// Shared f-tile layout: per f, 14 float2 slots (112 B), each value duplicated
// (v,v) so LDS.128 yields ready-to-use packed-broadcast operands.
__global__ __launch_bounds__(NTH, 3)
void pair_kernel(const float* __restrict__ t_fake,
                 const float* __restrict__ R_fake,
                 const float* __restrict__ r_buffer,
                 const float* __restrict__ t_buffer) {
    __shared__ __align__(16) float sf[FCHUNK * 28];          // 14 KB f-tile
    __shared__ __align__(16) uint2 s_fred[FCHUNK][8];        // 8 KB per-warp f results

    const int tid  = threadIdx.x;
    const int lane = tid & 31;
    const int warp = tid >> 5;

    const int cx = blockIdx.x & (NCH - 1);
    const int ry = blockIdx.x >> 5;
    const int fbase = cx * FCHUNK;
    const int rbase = ry * RBLK;

    // ---- stage duplicated f-tile (12 raw values per f) ----
    for (int i = tid; i < FCHUNK * 12; i += NTH) {
        int fl = i / 12, v = i - fl * 12;
        int fg = fbase + fl;
        float val = (v < 3) ? t_fake[fg * 3 + v] : R_fake[fg * 9 + (v - 3)];
        int slot = (v < 3) ? v : (v + 1);
        sf[fl * 28 + slot * 2 + 0] = val;
        sf[fl * 28 + slot * 2 + 1] = val;
    }
    for (int fl = tid; fl < FCHUNK; fl += NTH) {
        int fg = fbase + fl;
        float tx = t_fake[fg*3+0], ty = t_fake[fg*3+1], tz = t_fake[fg*3+2];
        float nf = fmaf(tx, tx, fmaf(ty, ty, tz * tz));
        sf[fl * 28 + 6] = nf;
        sf[fl * 28 + 7] = nf;
    }

    // ---- r-side registers: 2 rows as 1 packed pair ----
    const int r0 = rbase + tid * NT;
    const int ra = r0, rb = r0 + 1;
    unsigned long long tb2[3], Rr2[9], nr2;
    {
        float ax = t_buffer[ra*3+0], ay = t_buffer[ra*3+1], az = t_buffer[ra*3+2];
        float bx = t_buffer[rb*3+0], by = t_buffer[rb*3+1], bz = t_buffer[rb*3+2];
        tb2[0] = pk2(ax, bx);
        tb2[1] = pk2(ay, by);
        tb2[2] = pk2(az, bz);
        nr2 = pk2(fmaf(ax, ax, fmaf(ay, ay, az * az)),
                  fmaf(bx, bx, fmaf(by, by, bz * bz)));
        #pragma unroll
        for (int k = 0; k < 9; k++)
            Rr2[k] = pk2(r_buffer[ra*9+k], r_buffer[rb*9+k]);
    }
    __syncthreads();

    const float INF = __int_as_float(0x7f800000);
    const unsigned long long M2 = pk2(-2.0f, -2.0f);
    float minu0 = INF, minu1 = INF, maxtr0 = -INF, maxtr1 = -INF;

    #pragma unroll 2
    for (int f = 0; f < FCHUNK; f++) {
        const ulonglong2* fp = reinterpret_cast<const ulonglong2*>(sf + f * 28);
        ulonglong2 A = fp[0];   // tx2, ty2
        ulonglong2 B = fp[1];   // tz2, nf2
        ulonglong2 C = fp[2];   // R0, R1
        ulonglong2 D = fp[3];   // R2, R3
        ulonglong2 E = fp[4];   // R4, R5
        ulonglong2 F = fp[5];   // R6, R7
        ulonglong2 G = fp[6];   // R8, pad

        unsigned long long dot =
            ffma2(tb2[0], A.x, ffma2(tb2[1], A.y, fmul2(tb2[2], B.x)));
        unsigned long long u2 = ffma2(dot, M2, B.y);   // nf - 2 dot
        unsigned long long v2 = ffma2(dot, M2, nr2);   // nr - 2 dot
        unsigned long long tr = fmul2(Rr2[0], C.x);
        tr = ffma2(Rr2[1], C.y, tr);
        tr = ffma2(Rr2[2], D.x, tr);
        tr = ffma2(Rr2[3], D.y, tr);
        tr = ffma2(Rr2[4], E.x, tr);
        tr = ffma2(Rr2[5], E.y, tr);
        tr = ffma2(Rr2[6], F.x, tr);
        tr = ffma2(Rr2[7], F.y, tr);
        tr = ffma2(Rr2[8], G.x, tr);

        float ul, uh, vl, vh, tl, th;
        unpk2(u2, ul, uh);
        unpk2(v2, vl, vh);
        unpk2(tr, tl, th);

        minu0  = fminf(minu0, ul);
        minu1  = fminf(minu1, uh);
        maxtr0 = fmaxf(maxtr0, tl);
        maxtr1 = fmaxf(maxtr1, th);
        float fv = fminf(vl, vh);
        float ft = fmaxf(tl, th);

        // inverted-min encoding: both reductions are MAX, reset value 0
        unsigned ev = __reduce_max_sync(0xffffffffu, ~ford(fv));
        unsigned et = __reduce_max_sync(0xffffffffu, ford(ft));
        if (lane == 0) s_fred[f][warp] = make_uint2(ev, et);
    }

    // ---- per-r merge: fire-and-forget RED.MAX ----
    atomicMax(&g_ru[ra],  ~ford(minu0));
    atomicMax(&g_ru[rb],  ~ford(minu1));
    atomicMax(&g_rtr[ra],  ford(maxtr0));
    atomicMax(&g_rtr[rb],  ford(maxtr1));

    // ---- block combine of per-warp f results, then RED.MAX (2 per f) ----
    __syncthreads();
    if (tid < FCHUNK) {
        const uint4* p = reinterpret_cast<const uint4*>(&s_fred[tid][0]);
        unsigned ev = 0u, et = 0u;
        #pragma unroll
        for (int k = 0; k < 4; k++) {           // 4 x LDS.128 = 8 uint2
            uint4 q = p[k];
            ev = umax(ev, umax(q.x, q.z));
            et = umax(et, umax(q.y, q.w));
        }
        atomicMax(&g_fv[fbase + tid],  ev);
        atomicMax(&g_ftr[fbase + tid], et);
    }
}

// ---------------- epilogue: 96KB read, sqrt/acos, fixed-order sum ----------------
// Grid is exactly (NRK+NFK)/NTH = 48 blocks; gid < NRK -> r item, else f item.
// Each thread consumes its scratch words and writes 0 back (re-arms replay).
__global__ __launch_bounds__(NTH, 4)
void epilogue_kernel(const float* __restrict__ t_fake,
                     const float* __restrict__ t_buffer,
                     float* __restrict__ out) {
    const int tid = threadIdx.x;
    const int gid = blockIdx.x * NTH + tid;    // 0 .. NRK+NFK-1
    const int lane = tid & 31;
    const int warp = tid >> 5;

    float sAngR = 0.f, sSqR = 0.f, sAngF = 0.f, sSqF = 0.f;

    if (gid < NRK) {
        unsigned eu = g_ru[gid];
        unsigned et = g_rtr[gid];
        g_ru[gid] = 0u;
        g_rtr[gid] = 0u;
        float tx = t_buffer[gid*3+0], ty = t_buffer[gid*3+1], tz = t_buffer[gid*3+2];
        float nr = fmaf(tx, tx, fmaf(ty, ty, tz * tz));
        float td = fmaxf(nr + finv(~eu), 0.0f);
        sSqR = sqrtf(td + EPS_CH);
        float cs = 0.5f * (finv(et) - 1.0f);
        cs = fminf(fmaxf(cs, -1.0f + EPS_ACOS), 1.0f - EPS_ACOS);
        sAngR = acosf(cs);
    } else {
        const int f = gid - NRK;
        unsigned ev = g_fv[f];
        unsigned et = g_ftr[f];
        g_fv[f] = 0u;
        g_ftr[f] = 0u;
        float tx = t_fake[f*3+0], ty = t_fake[f*3+1], tz = t_fake[f*3+2];
        float nf = fmaf(tx, tx, fmaf(ty, ty, tz * tz));
        float td = fmaxf(nf + finv(~ev), 0.0f);
        sSqF = sqrtf(td + EPS_CH);
        float cs = 0.5f * (finv(et) - 1.0f);
        cs = fminf(fmaxf(cs, -1.0f + EPS_ACOS), 1.0f - EPS_ACOS);
        sAngF = acosf(cs);
    }

    // fixed-tree block reduction (deterministic)
    #pragma unroll
    for (int off = 16; off; off >>= 1) {
        sAngR += __shfl_xor_sync(0xffffffffu, sAngR, off);
        sSqR  += __shfl_xor_sync(0xffffffffu, sSqR,  off);
        sAngF += __shfl_xor_sync(0xffffffffu, sAngF, off);
        sSqF  += __shfl_xor_sync(0xffffffffu, sSqF,  off);
    }
    __shared__ float s_buf[NTH/32][4];
    __shared__ int s_fin;
    if (lane == 0) {
        s_buf[warp][0] = sAngR; s_buf[warp][1] = sSqR;
        s_buf[warp][2] = sAngF; s_buf[warp][3] = sSqF;
    }
    __syncthreads();

    if (tid == 0) {
        float a0 = 0.f, a1 = 0.f, a2 = 0.f, a3 = 0.f;
        #pragma unroll
        for (int i = 0; i < NTH/32; i++) {
            a0 += s_buf[i][0]; a1 += s_buf[i][1]; a2 += s_buf[i][2]; a3 += s_buf[i][3];
        }
        g_psum[0][blockIdx.x] = a0;
        g_psum[1][blockIdx.x] = a1;
        g_psum[2][blockIdx.x] = a2;
        g_psum[3][blockIdx.x] = a3;
        __threadfence();
        unsigned old = atomicAdd(&g_done, 1u);
        s_fin = ((old % EBLK) == (EBLK - 1u));
    }
    __syncthreads();

    // finisher: lane-parallel fixed-tree combine of 48 partials (warp 0)
    if (s_fin && warp == 0) {
        __threadfence();                            // acquire all psum writes
        float c[4];
        #pragma unroll
        for (int comp = 0; comp < 4; comp++) {
            float s = (lane < EBLK) ? g_psum[comp][lane] : 0.f;
            if (lane < EBLK - 32) s += g_psum[comp][lane + 32];
            #pragma unroll
            for (int off = 16; off; off >>= 1)
                s += __shfl_xor_sync(0xffffffffu, s, off);
            c[comp] = s;
        }
        if (lane == 0) {
            float rloss = c[2] / (float)NFK + c[0] / (float)NRK;
            float tloss = c[1] / (float)NRK + c[3] / (float)NFK;
            out[0] = rloss + tloss * PI_F;
        }
    }
}

// ---------------- launch ----------------
extern "C" void kernel_launch(void* const* d_in, const int* in_sizes, int n_in,
                              void* d_out, int out_size) {
    const float* t_fake   = nullptr;  // 4096*3
    const float* R_fake   = nullptr;  // 4096*9
    const float* r_buffer = nullptr;  // 8192*9
    const float* t_buffer = nullptr;  // 8192*3
    for (int i = 0; i < n_in; i++) {
        switch (in_sizes[i]) {
            case NFK*3: t_fake   = (const float*)d_in[i]; break;
            case NFK*9: R_fake   = (const float*)d_in[i]; break;
            case NRK*9: r_buffer = (const float*)d_in[i]; break;
            case NRK*3: t_buffer = (const float*)d_in[i]; break;
            default: break;
        }
    }

    pair_kernel<<<NTILES, NTH>>>(t_fake, R_fake, r_buffer, t_buffer);
    epilogue_kernel<<<EBLK, NTH>>>(t_fake, t_buffer, (float*)d_out);
}

// round 12
// speedup vs baseline: 1.3770x; 1.0437x over previous
#include <cuda_runtime.h>
#include <math.h>

// Problem constants (fixed shapes per reference)
#define NFK 4096
#define NRK 8192
#define FCHUNK 128              // f columns per tile
#define NCH (NFK/FCHUNK)        // 32 f-chunks

// rot kernel: 256 threads, 4 r/thread -> 1024 r per tile
#define RT_NTH 256
#define RT_NT 4
#define RT_RBLK (RT_NTH*RT_NT)  // 1024
#define RT_NRB (NRK/RT_RBLK)    // 8
#define RT_TILES (NCH*RT_NRB)   // 256

// trans kernel: 128 threads, 8 r/thread -> 1024 r per tile
#define TR_NTH 128
#define TR_NT 8
#define TR_RBLK (TR_NTH*TR_NT)  // 1024
#define TR_NRB (NRK/TR_RBLK)    // 8
#define TR_TILES (NCH*TR_NRB)   // 256

#define ENTH 256
#define EBLK 48                 // epilogue blocks: 48*256 = NRK+NFK exactly

#define EPS_CH   1e-5f
#define EPS_ACOS 1e-6f
#define PI_F     3.14159265358979323846f

// ---------------- static device scratch (allocation-free) ----------------
// All reduction scratch has reset value 0 ("no update"): zero-init on run 1,
// epilogue writes 0 back after consuming -> re-armed for every graph replay.
// g_done is monotonic, used mod EBLK (exactly EBLK increments per run).
__device__ unsigned g_done;            // finisher election counter
__device__ unsigned g_ru[NRK];         // max of ~ford(u)  -> min over f of u
__device__ unsigned g_rtr[NRK];        // max of  ford(tr) -> max over f of tr
__device__ unsigned g_fv[NFK];         // max of ~ford(v)  -> min over r of v
__device__ unsigned g_ftr[NFK];        // max of  ford(tr) -> max over r of tr
__device__ float    g_psum[4][EBLK];   // SoA per-epilogue-block partial sums

// Order-preserving float<->uint mapping (min/max in integer domain).
__device__ __forceinline__ unsigned ford(float f) {
    unsigned u = __float_as_uint(f);
    return (u & 0x80000000u) ? ~u : (u | 0x80000000u);
}
__device__ __forceinline__ float finv(unsigned u) {
    return __uint_as_float((u & 0x80000000u) ? (u & 0x7fffffffu) : ~u);
}

// ---------------- packed f32x2 helpers ----------------
__device__ __forceinline__ unsigned long long pk2(float a, float b) {
    unsigned long long r;
    asm("mov.b64 %0, {%1, %2};" : "=l"(r) : "f"(a), "f"(b));
    return r;
}
__device__ __forceinline__ void unpk2(unsigned long long v, float& lo, float& hi) {
    asm("mov.b64 {%0, %1}, %2;" : "=f"(lo), "=f"(hi) : "l"(v));
}
__device__ __forceinline__ unsigned long long ffma2(unsigned long long a,
                                                    unsigned long long b,
                                                    unsigned long long c) {
    unsigned long long d;
    asm("fma.rn.f32x2 %0, %1, %2, %3;" : "=l"(d) : "l"(a), "l"(b), "l"(c));
    return d;
}
__device__ __forceinline__ unsigned long long fmul2(unsigned long long a,
                                                    unsigned long long b) {
    unsigned long long d;
    asm("mul.rn.f32x2 %0, %1, %2;" : "=l"(d) : "l"(a), "l"(b));
    return d;
}

// =================== rotation kernel: trace GEMM + min/max ===================
// Shared f-tile: per f, 10 float2 slots (80 B): R0..R8 duplicated + pad.
__global__ __launch_bounds__(RT_NTH, 3)
void rot_kernel(const float* __restrict__ R_fake,
                const float* __restrict__ r_buffer) {
    __shared__ __align__(16) float sf[FCHUNK * 20];          // 10 KB
    __shared__ __align__(16) unsigned s_fred[FCHUNK][8];     // 4 KB per-warp ft

    const int tid  = threadIdx.x;
    const int lane = tid & 31;
    const int warp = tid >> 5;

    const int cx = blockIdx.x & (NCH - 1);
    const int ry = blockIdx.x >> 5;
    const int fbase = cx * FCHUNK;
    const int rbase = ry * RT_RBLK;

    // stage duplicated R tile: 2 threads per f (half 0: R0..R4, half 1: R5..R8)
    {
        int fl = tid >> 1, half = tid & 1;
        int fg = fbase + fl;
        int k0 = half ? 5 : 0, k1 = half ? 9 : 5;
        for (int k = k0; k < k1; k++) {
            float val = R_fake[fg * 9 + k];
            sf[fl * 20 + k * 2 + 0] = val;
            sf[fl * 20 + k * 2 + 1] = val;
        }
    }

    // r-side: 4 rows as 2 packed pairs (36 regs of R state)
    const int r0 = rbase + tid * RT_NT;
    unsigned long long Rr2[2][9];
    #pragma unroll
    for (int jp = 0; jp < 2; jp++) {
        int ra = r0 + 2 * jp, rb = ra + 1;
        #pragma unroll
        for (int k = 0; k < 9; k++)
            Rr2[jp][k] = pk2(r_buffer[ra*9+k], r_buffer[rb*9+k]);
    }
    __syncthreads();

    const float INF = __int_as_float(0x7f800000);
    float maxtr[RT_NT];
    #pragma unroll
    for (int j = 0; j < RT_NT; j++) maxtr[j] = -INF;

    #pragma unroll 2
    for (int f = 0; f < FCHUNK; f++) {
        const ulonglong2* fp = reinterpret_cast<const ulonglong2*>(sf + f * 20);
        ulonglong2 C = fp[0];   // R0, R1
        ulonglong2 D = fp[1];   // R2, R3
        ulonglong2 E = fp[2];   // R4, R5
        ulonglong2 F = fp[3];   // R6, R7
        ulonglong2 G = fp[4];   // R8, pad

        float ft = -INF;
        #pragma unroll
        for (int jp = 0; jp < 2; jp++) {
            unsigned long long tr = fmul2(Rr2[jp][0], C.x);
            tr = ffma2(Rr2[jp][1], C.y, tr);
            tr = ffma2(Rr2[jp][2], D.x, tr);
            tr = ffma2(Rr2[jp][3], D.y, tr);
            tr = ffma2(Rr2[jp][4], E.x, tr);
            tr = ffma2(Rr2[jp][5], E.y, tr);
            tr = ffma2(Rr2[jp][6], F.x, tr);
            tr = ffma2(Rr2[jp][7], F.y, tr);
            tr = ffma2(Rr2[jp][8], G.x, tr);
            float tl, th;
            unpk2(tr, tl, th);
            maxtr[2*jp+0] = fmaxf(maxtr[2*jp+0], tl);
            maxtr[2*jp+1] = fmaxf(maxtr[2*jp+1], th);
            ft = fmaxf(ft, fmaxf(tl, th));
        }
        unsigned et = __reduce_max_sync(0xffffffffu, ford(ft));
        if (lane == 0) s_fred[f][warp] = et;
    }

    // per-r merge: fire-and-forget RED.MAX
    #pragma unroll
    for (int j = 0; j < RT_NT; j++)
        atomicMax(&g_rtr[r0 + j], ford(maxtr[j]));

    // block combine of per-warp ft, then RED.MAX (1 per f)
    __syncthreads();
    if (tid < FCHUNK) {
        const uint4* p = reinterpret_cast<const uint4*>(&s_fred[tid][0]);
        uint4 a = p[0], b = p[1];                 // 2 x LDS.128 = 8 uints
        unsigned et = umax(umax(umax(a.x, a.y), umax(a.z, a.w)),
                           umax(umax(b.x, b.y), umax(b.z, b.w)));
        atomicMax(&g_ftr[fbase + tid], et);
    }
}

// ================ translation kernel: chamfer dots + min/min ================
// Shared f-tile: per f, 4 float2 slots (32 B): tx,ty,tz,nf duplicated.
__global__ __launch_bounds__(TR_NTH, 6)
void trans_kernel(const float* __restrict__ t_fake,
                  const float* __restrict__ t_buffer) {
    __shared__ __align__(16) float sf[FCHUNK * 8];           // 4 KB
    __shared__ __align__(16) unsigned s_fred[FCHUNK][4];     // 2 KB per-warp fv

    const int tid  = threadIdx.x;
    const int lane = tid & 31;
    const int warp = tid >> 5;

    const int cx = blockIdx.x & (NCH - 1);
    const int ry = blockIdx.x >> 5;
    const int fbase = cx * FCHUNK;
    const int rbase = ry * TR_RBLK;

    // stage duplicated t tile: one thread per f
    {
        int fg = fbase + tid;
        float tx = t_fake[fg*3+0], ty = t_fake[fg*3+1], tz = t_fake[fg*3+2];
        float nf = fmaf(tx, tx, fmaf(ty, ty, tz * tz));
        float* p = &sf[tid * 8];
        p[0] = tx; p[1] = tx; p[2] = ty; p[3] = ty;
        p[4] = tz; p[5] = tz; p[6] = nf; p[7] = nf;
    }

    // r-side: 8 rows as 4 packed pairs
    const int r0 = rbase + tid * TR_NT;
    unsigned long long tb2[4][3], nr2[4];
    #pragma unroll
    for (int jp = 0; jp < 4; jp++) {
        int ra = r0 + 2 * jp, rb = ra + 1;
        float ax = t_buffer[ra*3+0], ay = t_buffer[ra*3+1], az = t_buffer[ra*3+2];
        float bx = t_buffer[rb*3+0], by = t_buffer[rb*3+1], bz = t_buffer[rb*3+2];
        tb2[jp][0] = pk2(ax, bx);
        tb2[jp][1] = pk2(ay, by);
        tb2[jp][2] = pk2(az, bz);
        nr2[jp] = pk2(fmaf(ax, ax, fmaf(ay, ay, az * az)),
                      fmaf(bx, bx, fmaf(by, by, bz * bz)));
    }
    __syncthreads();

    const float INF = __int_as_float(0x7f800000);
    const unsigned long long M2 = pk2(-2.0f, -2.0f);
    float minu[TR_NT];
    #pragma unroll
    for (int j = 0; j < TR_NT; j++) minu[j] = INF;

    #pragma unroll 2
    for (int f = 0; f < FCHUNK; f++) {
        const ulonglong2* fp = reinterpret_cast<const ulonglong2*>(sf + f * 8);
        ulonglong2 A = fp[0];   // tx2, ty2
        ulonglong2 B = fp[1];   // tz2, nf2

        float fv = INF;
        #pragma unroll
        for (int jp = 0; jp < 4; jp++) {
            unsigned long long dot =
                ffma2(tb2[jp][0], A.x, ffma2(tb2[jp][1], A.y, fmul2(tb2[jp][2], B.x)));
            unsigned long long u2 = ffma2(dot, M2, B.y);   // nf - 2 dot
            unsigned long long v2 = ffma2(dot, M2, nr2[jp]); // nr - 2 dot
            float ul, uh, vl, vh;
            unpk2(u2, ul, uh);
            unpk2(v2, vl, vh);
            minu[2*jp+0] = fminf(minu[2*jp+0], ul);
            minu[2*jp+1] = fminf(minu[2*jp+1], uh);
            fv = fminf(fv, fminf(vl, vh));
        }
        unsigned ev = __reduce_max_sync(0xffffffffu, ~ford(fv));
        if (lane == 0) s_fred[f][warp] = ev;
    }

    // per-r merge: fire-and-forget RED.MAX
    #pragma unroll
    for (int j = 0; j < TR_NT; j++)
        atomicMax(&g_ru[r0 + j], ~ford(minu[j]));

    // block combine of per-warp fv, then RED.MAX (1 per f)
    __syncthreads();
    {
        const uint4* p = reinterpret_cast<const uint4*>(&s_fred[tid][0]);
        uint4 a = p[0];                            // 1 x LDS.128 = 4 uints
        unsigned ev = umax(umax(a.x, a.y), umax(a.z, a.w));
        atomicMax(&g_fv[fbase + tid], ev);
    }
}

// ---------------- epilogue: 96KB read, sqrt/acos, fixed-order sum ----------------
// Grid is exactly (NRK+NFK)/ENTH = 48 blocks; gid < NRK -> r item, else f item.
// Each thread consumes its scratch words and writes 0 back (re-arms replay).
__global__ __launch_bounds__(ENTH, 4)
void epilogue_kernel(const float* __restrict__ t_fake,
                     const float* __restrict__ t_buffer,
                     float* __restrict__ out) {
    const int tid = threadIdx.x;
    const int gid = blockIdx.x * ENTH + tid;    // 0 .. NRK+NFK-1
    const int lane = tid & 31;
    const int warp = tid >> 5;

    float sAngR = 0.f, sSqR = 0.f, sAngF = 0.f, sSqF = 0.f;

    if (gid < NRK) {
        unsigned eu = g_ru[gid];
        unsigned et = g_rtr[gid];
        g_ru[gid] = 0u;
        g_rtr[gid] = 0u;
        float tx = t_buffer[gid*3+0], ty = t_buffer[gid*3+1], tz = t_buffer[gid*3+2];
        float nr = fmaf(tx, tx, fmaf(ty, ty, tz * tz));
        float td = fmaxf(nr + finv(~eu), 0.0f);
        sSqR = sqrtf(td + EPS_CH);
        float cs = 0.5f * (finv(et) - 1.0f);
        cs = fminf(fmaxf(cs, -1.0f + EPS_ACOS), 1.0f - EPS_ACOS);
        sAngR = acosf(cs);
    } else {
        const int f = gid - NRK;
        unsigned ev = g_fv[f];
        unsigned et = g_ftr[f];
        g_fv[f] = 0u;
        g_ftr[f] = 0u;
        float tx = t_fake[f*3+0], ty = t_fake[f*3+1], tz = t_fake[f*3+2];
        float nf = fmaf(tx, tx, fmaf(ty, ty, tz * tz));
        float td = fmaxf(nf + finv(~ev), 0.0f);
        sSqF = sqrtf(td + EPS_CH);
        float cs = 0.5f * (finv(et) - 1.0f);
        cs = fminf(fmaxf(cs, -1.0f + EPS_ACOS), 1.0f - EPS_ACOS);
        sAngF = acosf(cs);
    }

    // fixed-tree block reduction (deterministic)
    #pragma unroll
    for (int off = 16; off; off >>= 1) {
        sAngR += __shfl_xor_sync(0xffffffffu, sAngR, off);
        sSqR  += __shfl_xor_sync(0xffffffffu, sSqR,  off);
        sAngF += __shfl_xor_sync(0xffffffffu, sAngF, off);
        sSqF  += __shfl_xor_sync(0xffffffffu, sSqF,  off);
    }
    __shared__ float s_buf[ENTH/32][4];
    __shared__ int s_fin;
    if (lane == 0) {
        s_buf[warp][0] = sAngR; s_buf[warp][1] = sSqR;
        s_buf[warp][2] = sAngF; s_buf[warp][3] = sSqF;
    }
    __syncthreads();

    if (tid == 0) {
        float a0 = 0.f, a1 = 0.f, a2 = 0.f, a3 = 0.f;
        #pragma unroll
        for (int i = 0; i < ENTH/32; i++) {
            a0 += s_buf[i][0]; a1 += s_buf[i][1]; a2 += s_buf[i][2]; a3 += s_buf[i][3];
        }
        g_psum[0][blockIdx.x] = a0;
        g_psum[1][blockIdx.x] = a1;
        g_psum[2][blockIdx.x] = a2;
        g_psum[3][blockIdx.x] = a3;
        __threadfence();
        unsigned old = atomicAdd(&g_done, 1u);
        s_fin = ((old % EBLK) == (EBLK - 1u));
    }
    __syncthreads();

    // finisher: lane-parallel fixed-tree combine of 48 partials (warp 0)
    if (s_fin && warp == 0) {
        __threadfence();                            // acquire all psum writes
        float c[4];
        #pragma unroll
        for (int comp = 0; comp < 4; comp++) {
            float s = (lane < EBLK) ? g_psum[comp][lane] : 0.f;
            if (lane < EBLK - 32) s += g_psum[comp][lane + 32];
            #pragma unroll
            for (int off = 16; off; off >>= 1)
                s += __shfl_xor_sync(0xffffffffu, s, off);
            c[comp] = s;
        }
        if (lane == 0) {
            float rloss = c[2] / (float)NFK + c[0] / (float)NRK;
            float tloss = c[1] / (float)NRK + c[3] / (float)NFK;
            out[0] = rloss + tloss * PI_F;
        }
    }
}

// ---------------- launch ----------------
extern "C" void kernel_launch(void* const* d_in, const int* in_sizes, int n_in,
                              void* d_out, int out_size) {
    const float* t_fake   = nullptr;  // 4096*3
    const float* R_fake   = nullptr;  // 4096*9
    const float* r_buffer = nullptr;  // 8192*9
    const float* t_buffer = nullptr;  // 8192*3
    for (int i = 0; i < n_in; i++) {
        switch (in_sizes[i]) {
            case NFK*3: t_fake   = (const float*)d_in[i]; break;
            case NFK*9: R_fake   = (const float*)d_in[i]; break;
            case NRK*9: r_buffer = (const float*)d_in[i]; break;
            case NRK*3: t_buffer = (const float*)d_in[i]; break;
            default: break;
        }
    }

    rot_kernel<<<RT_TILES, RT_NTH>>>(R_fake, r_buffer);
    trans_kernel<<<TR_TILES, TR_NTH>>>(t_fake, t_buffer);
    epilogue_kernel<<<EBLK, ENTH>>>(t_fake, t_buffer, (float*)d_out);
}

// round 13
// speedup vs baseline: 1.3901x; 1.0095x over previous
#include <cuda_runtime.h>
#include <math.h>

// Problem constants (fixed shapes per reference)
#define NFK 4096
#define NRK 8192
#define NTH 256
#define FCH 64                  // f columns per tile (small -> many blocks)
#define NCH (NFK/FCH)           // 64 f-chunks

// rot tiles: 256 threads, 4 r/thread -> 1024 r per tile
#define RT_NT 4
#define RT_RBLK (NTH*RT_NT)     // 1024
#define RT_NRB (NRK/RT_RBLK)    // 8
#define RT_TILES (NCH*RT_NRB)   // 512

// trans tiles: 256 threads, 8 r/thread -> 2048 r per tile
#define TR_NT 8
#define TR_RBLK (NTH*TR_NT)     // 2048
#define TR_NRB (NRK/TR_RBLK)    // 4
#define TR_TILES (NCH*TR_NRB)   // 256

#define GRID (RT_TILES + TR_TILES)   // 768

#define EBLK 48                 // epilogue blocks: 48*256 = NRK+NFK exactly

#define EPS_CH   1e-5f
#define EPS_ACOS 1e-6f
#define PI_F     3.14159265358979323846f

// ---------------- static device scratch (allocation-free) ----------------
// All reduction scratch has reset value 0 ("no update"): zero-init on run 1,
// epilogue writes 0 back after consuming -> re-armed for every graph replay.
// g_done is monotonic, used mod EBLK (exactly EBLK increments per run).
__device__ unsigned g_done;            // finisher election counter
__device__ unsigned g_ru[NRK];         // max of ~ford(u)  -> min over f of u
__device__ unsigned g_rtr[NRK];        // max of  ford(tr) -> max over f of tr
__device__ unsigned g_fv[NFK];         // max of ~ford(v)  -> min over r of v
__device__ unsigned g_ftr[NFK];        // max of  ford(tr) -> max over r of tr
__device__ float    g_psum[4][EBLK];   // SoA per-epilogue-block partial sums

// Order-preserving float<->uint mapping (min/max in integer domain).
__device__ __forceinline__ unsigned ford(float f) {
    unsigned u = __float_as_uint(f);
    return (u & 0x80000000u) ? ~u : (u | 0x80000000u);
}
__device__ __forceinline__ float finv(unsigned u) {
    return __uint_as_float((u & 0x80000000u) ? (u & 0x7fffffffu) : ~u);
}

// ---------------- packed f32x2 helpers ----------------
__device__ __forceinline__ unsigned long long pk2(float a, float b) {
    unsigned long long r;
    asm("mov.b64 %0, {%1, %2};" : "=l"(r) : "f"(a), "f"(b));
    return r;
}
__device__ __forceinline__ void unpk2(unsigned long long v, float& lo, float& hi) {
    asm("mov.b64 {%0, %1}, %2;" : "=f"(lo), "=f"(hi) : "l"(v));
}
__device__ __forceinline__ unsigned long long ffma2(unsigned long long a,
                                                    unsigned long long b,
                                                    unsigned long long c) {
    unsigned long long d;
    asm("fma.rn.f32x2 %0, %1, %2, %3;" : "=l"(d) : "l"(a), "l"(b), "l"(c));
    return d;
}
__device__ __forceinline__ unsigned long long fmul2(unsigned long long a,
                                                    unsigned long long b) {
    unsigned long long d;
    asm("mul.rn.f32x2 %0, %1, %2;" : "=l"(d) : "l"(a), "l"(b));
    return d;
}

// ============ fused pair kernel: rot tiles then trans tiles ============
__global__ __launch_bounds__(NTH, 3)
void pair_kernel(const float* __restrict__ t_fake,
                 const float* __restrict__ R_fake,
                 const float* __restrict__ r_buffer,
                 const float* __restrict__ t_buffer) {
    // union of both layouts; rot is the larger user (5 KB + 2 KB)
    __shared__ __align__(16) float    sf[FCH * 20];      // rot: 10 f2/f; trans: 4 f2/f
    __shared__ __align__(16) unsigned s_fred[FCH][8];    // per-warp per-f results

    const int tid  = threadIdx.x;
    const int lane = tid & 31;
    const int warp = tid >> 5;

    if (blockIdx.x < RT_TILES) {
        // ================= rotation tile =================
        const int bx = blockIdx.x;
        const int cx = bx & (NCH - 1);
        const int ry = bx >> 6;
        const int fbase = cx * FCH;
        const int rbase = ry * RT_RBLK;

        // stage duplicated R tile: 4 threads per f, strided k
        {
            int fl = tid >> 2, q = tid & 3;
            int fg = fbase + fl;
            for (int k = q; k < 9; k += 4) {
                float val = R_fake[fg * 9 + k];
                sf[fl * 20 + k * 2 + 0] = val;
                sf[fl * 20 + k * 2 + 1] = val;
            }
        }

        const int r0 = rbase + tid * RT_NT;
        unsigned long long Rr2[2][9];
        #pragma unroll
        for (int jp = 0; jp < 2; jp++) {
            int ra = r0 + 2 * jp, rb = ra + 1;
            #pragma unroll
            for (int k = 0; k < 9; k++)
                Rr2[jp][k] = pk2(r_buffer[ra*9+k], r_buffer[rb*9+k]);
        }
        __syncthreads();

        const float INF = __int_as_float(0x7f800000);
        float maxtr[RT_NT];
        #pragma unroll
        for (int j = 0; j < RT_NT; j++) maxtr[j] = -INF;

        #pragma unroll 2
        for (int f = 0; f < FCH; f++) {
            const ulonglong2* fp = reinterpret_cast<const ulonglong2*>(sf + f * 20);
            ulonglong2 C = fp[0];   // R0, R1
            ulonglong2 D = fp[1];   // R2, R3
            ulonglong2 E = fp[2];   // R4, R5
            ulonglong2 F = fp[3];   // R6, R7
            ulonglong2 G = fp[4];   // R8, pad

            float ft = -INF;
            #pragma unroll
            for (int jp = 0; jp < 2; jp++) {
                unsigned long long tr = fmul2(Rr2[jp][0], C.x);
                tr = ffma2(Rr2[jp][1], C.y, tr);
                tr = ffma2(Rr2[jp][2], D.x, tr);
                tr = ffma2(Rr2[jp][3], D.y, tr);
                tr = ffma2(Rr2[jp][4], E.x, tr);
                tr = ffma2(Rr2[jp][5], E.y, tr);
                tr = ffma2(Rr2[jp][6], F.x, tr);
                tr = ffma2(Rr2[jp][7], F.y, tr);
                tr = ffma2(Rr2[jp][8], G.x, tr);
                float tl, th;
                unpk2(tr, tl, th);
                maxtr[2*jp+0] = fmaxf(maxtr[2*jp+0], tl);
                maxtr[2*jp+1] = fmaxf(maxtr[2*jp+1], th);
                ft = fmaxf(ft, fmaxf(tl, th));
            }
            unsigned et = __reduce_max_sync(0xffffffffu, ford(ft));
            if (lane == 0) s_fred[f][warp] = et;
        }

        #pragma unroll
        for (int j = 0; j < RT_NT; j++)
            atomicMax(&g_rtr[r0 + j], ford(maxtr[j]));

        __syncthreads();
        if (tid < FCH) {
            const uint4* p = reinterpret_cast<const uint4*>(&s_fred[tid][0]);
            uint4 a = p[0], b = p[1];
            unsigned et = umax(umax(umax(a.x, a.y), umax(a.z, a.w)),
                               umax(umax(b.x, b.y), umax(b.z, b.w)));
            atomicMax(&g_ftr[fbase + tid], et);
        }
    } else {
        // ================= translation tile =================
        const int bx = blockIdx.x - RT_TILES;
        const int cx = bx & (NCH - 1);
        const int ry = bx >> 6;
        const int fbase = cx * FCH;
        const int rbase = ry * TR_RBLK;

        // stage duplicated t tile: one thread per f (tid < 64)
        if (tid < FCH) {
            int fg = fbase + tid;
            float tx = t_fake[fg*3+0], ty = t_fake[fg*3+1], tz = t_fake[fg*3+2];
            float nf = fmaf(tx, tx, fmaf(ty, ty, tz * tz));
            float* p = &sf[tid * 8];
            p[0] = tx; p[1] = tx; p[2] = ty; p[3] = ty;
            p[4] = tz; p[5] = tz; p[6] = nf; p[7] = nf;
        }

        const int r0 = rbase + tid * TR_NT;
        unsigned long long tb2[4][3], nr2[4];
        #pragma unroll
        for (int jp = 0; jp < 4; jp++) {
            int ra = r0 + 2 * jp, rb = ra + 1;
            float ax = t_buffer[ra*3+0], ay = t_buffer[ra*3+1], az = t_buffer[ra*3+2];
            float bx2 = t_buffer[rb*3+0], by = t_buffer[rb*3+1], bz = t_buffer[rb*3+2];
            tb2[jp][0] = pk2(ax, bx2);
            tb2[jp][1] = pk2(ay, by);
            tb2[jp][2] = pk2(az, bz);
            nr2[jp] = pk2(fmaf(ax, ax, fmaf(ay, ay, az * az)),
                          fmaf(bx2, bx2, fmaf(by, by, bz * bz)));
        }
        __syncthreads();

        const float INF = __int_as_float(0x7f800000);
        const unsigned long long M2 = pk2(-2.0f, -2.0f);
        float minu[TR_NT];
        #pragma unroll
        for (int j = 0; j < TR_NT; j++) minu[j] = INF;

        #pragma unroll 2
        for (int f = 0; f < FCH; f++) {
            const ulonglong2* fp = reinterpret_cast<const ulonglong2*>(sf + f * 8);
            ulonglong2 A = fp[0];   // tx2, ty2
            ulonglong2 B = fp[1];   // tz2, nf2

            float fv = INF;
            #pragma unroll
            for (int jp = 0; jp < 4; jp++) {
                unsigned long long dot =
                    ffma2(tb2[jp][0], A.x, ffma2(tb2[jp][1], A.y, fmul2(tb2[jp][2], B.x)));
                unsigned long long u2 = ffma2(dot, M2, B.y);     // nf - 2 dot
                unsigned long long v2 = ffma2(dot, M2, nr2[jp]); // nr - 2 dot
                float ul, uh, vl, vh;
                unpk2(u2, ul, uh);
                unpk2(v2, vl, vh);
                minu[2*jp+0] = fminf(minu[2*jp+0], ul);
                minu[2*jp+1] = fminf(minu[2*jp+1], uh);
                fv = fminf(fv, fminf(vl, vh));
            }
            unsigned ev = __reduce_max_sync(0xffffffffu, ~ford(fv));
            if (lane == 0) s_fred[f][warp] = ev;
        }

        #pragma unroll
        for (int j = 0; j < TR_NT; j++)
            atomicMax(&g_ru[r0 + j], ~ford(minu[j]));

        __syncthreads();
        if (tid < FCH) {
            const uint4* p = reinterpret_cast<const uint4*>(&s_fred[tid][0]);
            uint4 a = p[0], b = p[1];
            unsigned ev = umax(umax(umax(a.x, a.y), umax(a.z, a.w)),
                               umax(umax(b.x, b.y), umax(b.z, b.w)));
            atomicMax(&g_fv[fbase + tid], ev);
        }
    }
}

// ---------------- epilogue: 96KB read, sqrt/acos, fixed-order sum ----------------
// Grid is exactly (NRK+NFK)/NTH = 48 blocks; gid < NRK -> r item, else f item.
// Each thread consumes its scratch words and writes 0 back (re-arms replay).
__global__ __launch_bounds__(NTH, 4)
void epilogue_kernel(const float* __restrict__ t_fake,
                     const float* __restrict__ t_buffer,
                     float* __restrict__ out) {
    const int tid = threadIdx.x;
    const int gid = blockIdx.x * NTH + tid;    // 0 .. NRK+NFK-1
    const int lane = tid & 31;
    const int warp = tid >> 5;

    float sAngR = 0.f, sSqR = 0.f, sAngF = 0.f, sSqF = 0.f;

    if (gid < NRK) {
        unsigned eu = g_ru[gid];
        unsigned et = g_rtr[gid];
        g_ru[gid] = 0u;
        g_rtr[gid] = 0u;
        float tx = t_buffer[gid*3+0], ty = t_buffer[gid*3+1], tz = t_buffer[gid*3+2];
        float nr = fmaf(tx, tx, fmaf(ty, ty, tz * tz));
        float td = fmaxf(nr + finv(~eu), 0.0f);
        sSqR = sqrtf(td + EPS_CH);
        float cs = 0.5f * (finv(et) - 1.0f);
        cs = fminf(fmaxf(cs, -1.0f + EPS_ACOS), 1.0f - EPS_ACOS);
        sAngR = acosf(cs);
    } else {
        const int f = gid - NRK;
        unsigned ev = g_fv[f];
        unsigned et = g_ftr[f];
        g_fv[f] = 0u;
        g_ftr[f] = 0u;
        float tx = t_fake[f*3+0], ty = t_fake[f*3+1], tz = t_fake[f*3+2];
        float nf = fmaf(tx, tx, fmaf(ty, ty, tz * tz));
        float td = fmaxf(nf + finv(~ev), 0.0f);
        sSqF = sqrtf(td + EPS_CH);
        float cs = 0.5f * (finv(et) - 1.0f);
        cs = fminf(fmaxf(cs, -1.0f + EPS_ACOS), 1.0f - EPS_ACOS);
        sAngF = acosf(cs);
    }

    // fixed-tree block reduction (deterministic)
    #pragma unroll
    for (int off = 16; off; off >>= 1) {
        sAngR += __shfl_xor_sync(0xffffffffu, sAngR, off);
        sSqR  += __shfl_xor_sync(0xffffffffu, sSqR,  off);
        sAngF += __shfl_xor_sync(0xffffffffu, sAngF, off);
        sSqF  += __shfl_xor_sync(0xffffffffu, sSqF,  off);
    }
    __shared__ float s_buf[NTH/32][4];
    __shared__ int s_fin;
    if (lane == 0) {
        s_buf[warp][0] = sAngR; s_buf[warp][1] = sSqR;
        s_buf[warp][2] = sAngF; s_buf[warp][3] = sSqF;
    }
    __syncthreads();

    if (tid == 0) {
        float a0 = 0.f, a1 = 0.f, a2 = 0.f, a3 = 0.f;
        #pragma unroll
        for (int i = 0; i < NTH/32; i++) {
            a0 += s_buf[i][0]; a1 += s_buf[i][1]; a2 += s_buf[i][2]; a3 += s_buf[i][3];
        }
        g_psum[0][blockIdx.x] = a0;
        g_psum[1][blockIdx.x] = a1;
        g_psum[2][blockIdx.x] = a2;
        g_psum[3][blockIdx.x] = a3;
        __threadfence();
        unsigned old = atomicAdd(&g_done, 1u);
        s_fin = ((old % EBLK) == (EBLK - 1u));
    }
    __syncthreads();

    // finisher: lane-parallel fixed-tree combine of 48 partials (warp 0)
    if (s_fin && warp == 0) {
        __threadfence();                            // acquire all psum writes
        float c[4];
        #pragma unroll
        for (int comp = 0; comp < 4; comp++) {
            float s = (lane < EBLK) ? g_psum[comp][lane] : 0.f;
            if (lane < EBLK - 32) s += g_psum[comp][lane + 32];
            #pragma unroll
            for (int off = 16; off; off >>= 1)
                s += __shfl_xor_sync(0xffffffffu, s, off);
            c[comp] = s;
        }
        if (lane == 0) {
            float rloss = c[2] / (float)NFK + c[0] / (float)NRK;
            float tloss = c[1] / (float)NRK + c[3] / (float)NFK;
            out[0] = rloss + tloss * PI_F;
        }
    }
}

// ---------------- launch ----------------
extern "C" void kernel_launch(void* const* d_in, const int* in_sizes, int n_in,
                              void* d_out, int out_size) {
    const float* t_fake   = nullptr;  // 4096*3
    const float* R_fake   = nullptr;  // 4096*9
    const float* r_buffer = nullptr;  // 8192*9
    const float* t_buffer = nullptr;  // 8192*3
    for (int i = 0; i < n_in; i++) {
        switch (in_sizes[i]) {
            case NFK*3: t_fake   = (const float*)d_in[i]; break;
            case NFK*9: R_fake   = (const float*)d_in[i]; break;
            case NRK*9: r_buffer = (const float*)d_in[i]; break;
            case NRK*3: t_buffer = (const float*)d_in[i]; break;
            default: break;
        }
    }

    pair_kernel<<<GRID, NTH>>>(t_fake, R_fake, r_buffer, t_buffer);
    epilogue_kernel<<<EBLK, NTH>>>(t_fake, t_buffer, (float*)d_out);
}

// round 14
// speedup vs baseline: 1.4542x; 1.0461x over previous
#include <cuda_runtime.h>
#include <math.h>

// Problem constants (fixed shapes per reference)
#define NFK 4096
#define NRK 8192
#define NTH 256
#define FCH 64                  // f columns per tile
#define NCH (NFK/FCH)           // 64 f-chunks

// rot tiles: 256 threads, 4 r/thread -> 1024 r per tile
#define RT_NT 4
#define RT_RBLK (NTH*RT_NT)     // 1024
#define RT_NRB (NRK/RT_RBLK)    // 8
#define RT_TILES (NCH*RT_NRB)   // 512

// trans tiles: 256 threads, 8 r/thread -> 2048 r per tile
#define TR_NT 8
#define TR_RBLK (NTH*TR_NT)     // 2048
#define TR_NRB (NRK/TR_RBLK)    // 4
#define TR_TILES (NCH*TR_NRB)   // 256

#define GRID (RT_TILES + TR_TILES)   // 768

#define EBLK 48                 // epilogue blocks: 48*256 = NRK+NFK exactly

#define EPS_CH   1e-5f
#define EPS_ACOS 1e-6f
#define PI_F     3.14159265358979323846f

// ---------------- static device scratch (allocation-free) ----------------
// Encodings (all positive, reset value 0 = "no update"; epilogue re-zeros):
//   g_ru[r]  = max of ~bits(min_f w)      -> w = squared distance (>=0)
//   g_fv[f]  = max of ~bits(min_r w)
//   g_rtr[r] = max of  bits(max_f tr')    -> tr' = trace + 1 in [0,4]
//   g_ftr[f] = max of  bits(max_r tr')
// Raw float bits of non-negative floats are order-preserving as uints.
__device__ unsigned g_done;            // finisher election counter (monotonic)
__device__ unsigned g_ru[NRK];
__device__ unsigned g_rtr[NRK];
__device__ unsigned g_fv[NFK];
__device__ unsigned g_ftr[NFK];
__device__ float    g_psum[4][EBLK];   // SoA per-epilogue-block partial sums

// ---------------- packed f32x2 helpers ----------------
__device__ __forceinline__ unsigned long long pk2(float a, float b) {
    unsigned long long r;
    asm("mov.b64 %0, {%1, %2};" : "=l"(r) : "f"(a), "f"(b));
    return r;
}
__device__ __forceinline__ void unpk2(unsigned long long v, float& lo, float& hi) {
    asm("mov.b64 {%0, %1}, %2;" : "=f"(lo), "=f"(hi) : "l"(v));
}
__device__ __forceinline__ unsigned long long ffma2(unsigned long long a,
                                                    unsigned long long b,
                                                    unsigned long long c) {
    unsigned long long d;
    asm("fma.rn.f32x2 %0, %1, %2, %3;" : "=l"(d) : "l"(a), "l"(b), "l"(c));
    return d;
}
__device__ __forceinline__ unsigned long long fmul2(unsigned long long a,
                                                    unsigned long long b) {
    unsigned long long d;
    asm("mul.rn.f32x2 %0, %1, %2;" : "=l"(d) : "l"(a), "l"(b));
    return d;
}
__device__ __forceinline__ unsigned long long fadd2(unsigned long long a,
                                                    unsigned long long b) {
    unsigned long long d;
    asm("add.rn.f32x2 %0, %1, %2;" : "=l"(d) : "l"(a), "l"(b));
    return d;
}

// ============ fused pair kernel: rot tiles then trans tiles ============
__global__ __launch_bounds__(NTH, 3)
void pair_kernel(const float* __restrict__ t_fake,
                 const float* __restrict__ R_fake,
                 const float* __restrict__ r_buffer,
                 const float* __restrict__ t_buffer) {
    __shared__ __align__(16) float    sf[FCH * 20];      // rot: 10 f2/f; trans: 4 f2/f
    __shared__ __align__(16) unsigned s_fred[FCH][8];    // per-warp per-f results

    const int tid  = threadIdx.x;
    const int lane = tid & 31;
    const int warp = tid >> 5;

    if (blockIdx.x < RT_TILES) {
        // ================= rotation tile =================
        const int bx = blockIdx.x;
        const int cx = bx & (NCH - 1);
        const int ry = bx >> 6;
        const int fbase = cx * FCH;
        const int rbase = ry * RT_RBLK;

        // stage duplicated R tile: 4 threads per f, strided k
        {
            int fl = tid >> 2, q = tid & 3;
            int fg = fbase + fl;
            for (int k = q; k < 9; k += 4) {
                float val = R_fake[fg * 9 + k];
                sf[fl * 20 + k * 2 + 0] = val;
                sf[fl * 20 + k * 2 + 1] = val;
            }
        }

        const int r0 = rbase + tid * RT_NT;
        unsigned long long Rr2[2][9];
        #pragma unroll
        for (int jp = 0; jp < 2; jp++) {
            int ra = r0 + 2 * jp, rb = ra + 1;
            #pragma unroll
            for (int k = 0; k < 9; k++)
                Rr2[jp][k] = pk2(r_buffer[ra*9+k], r_buffer[rb*9+k]);
        }
        __syncthreads();

        const float INF = __int_as_float(0x7f800000);
        const unsigned long long ONE2 = pk2(1.0f, 1.0f);
        float maxtr[RT_NT];
        #pragma unroll
        for (int j = 0; j < RT_NT; j++) maxtr[j] = -INF;

        #pragma unroll 2
        for (int f = 0; f < FCH; f++) {
            const ulonglong2* fp = reinterpret_cast<const ulonglong2*>(sf + f * 20);
            ulonglong2 C = fp[0];   // R0, R1
            ulonglong2 D = fp[1];   // R2, R3
            ulonglong2 E = fp[2];   // R4, R5
            ulonglong2 F = fp[3];   // R6, R7
            ulonglong2 G = fp[4];   // R8, pad

            float ft = -INF;
            #pragma unroll
            for (int jp = 0; jp < 2; jp++) {
                // tr' = trace + 1 via two parallel chains (shallower dep)
                unsigned long long trA = ffma2(Rr2[jp][0], C.x, ONE2);
                trA = ffma2(Rr2[jp][1], C.y, trA);
                trA = ffma2(Rr2[jp][2], D.x, trA);
                trA = ffma2(Rr2[jp][3], D.y, trA);
                unsigned long long trB = fmul2(Rr2[jp][4], E.x);
                trB = ffma2(Rr2[jp][5], E.y, trB);
                trB = ffma2(Rr2[jp][6], F.x, trB);
                trB = ffma2(Rr2[jp][7], F.y, trB);
                trB = ffma2(Rr2[jp][8], G.x, trB);
                unsigned long long tr = fadd2(trA, trB);
                float tl, th;
                unpk2(tr, tl, th);
                maxtr[2*jp+0] = fmaxf(maxtr[2*jp+0], tl);
                maxtr[2*jp+1] = fmaxf(maxtr[2*jp+1], th);
                ft = fmaxf(ft, fmaxf(tl, th));
            }
            // tr' >= 0 -> raw bits are order-preserving
            unsigned et = __reduce_max_sync(0xffffffffu, __float_as_uint(ft));
            if (lane == 0) s_fred[f][warp] = et;
        }

        #pragma unroll
        for (int j = 0; j < RT_NT; j++)
            atomicMax(&g_rtr[r0 + j], __float_as_uint(maxtr[j]));

        __syncthreads();
        if (tid < FCH) {
            const uint4* p = reinterpret_cast<const uint4*>(&s_fred[tid][0]);
            uint4 a = p[0], b = p[1];
            unsigned et = umax(umax(umax(a.x, a.y), umax(a.z, a.w)),
                               umax(umax(b.x, b.y), umax(b.z, b.w)));
            atomicMax(&g_ftr[fbase + tid], et);
        }
    } else {
        // ================= translation tile =================
        const int bx = blockIdx.x - RT_TILES;
        const int cx = bx & (NCH - 1);
        const int ry = bx >> 6;
        const int fbase = cx * FCH;
        const int rbase = ry * TR_RBLK;

        // stage duplicated t tile: one thread per f (tid < 64)
        if (tid < FCH) {
            int fg = fbase + tid;
            float tx = t_fake[fg*3+0], ty = t_fake[fg*3+1], tz = t_fake[fg*3+2];
            float nf = fmaf(tx, tx, fmaf(ty, ty, tz * tz));
            float* p = &sf[tid * 8];
            p[0] = tx; p[1] = tx; p[2] = ty; p[3] = ty;
            p[4] = tz; p[5] = tz; p[6] = nf; p[7] = nf;
        }

        const int r0 = rbase + tid * TR_NT;
        unsigned long long tb2[4][3], nr2[4];
        #pragma unroll
        for (int jp = 0; jp < 4; jp++) {
            int ra = r0 + 2 * jp, rb = ra + 1;
            float ax = t_buffer[ra*3+0], ay = t_buffer[ra*3+1], az = t_buffer[ra*3+2];
            float bx2 = t_buffer[rb*3+0], by = t_buffer[rb*3+1], bz = t_buffer[rb*3+2];
            tb2[jp][0] = pk2(ax, bx2);
            tb2[jp][1] = pk2(ay, by);
            tb2[jp][2] = pk2(az, bz);
            nr2[jp] = pk2(fmaf(ax, ax, fmaf(ay, ay, az * az)),
                          fmaf(bx2, bx2, fmaf(by, by, bz * bz)));
        }
        __syncthreads();

        const float INF = __int_as_float(0x7f800000);
        const unsigned long long M2 = pk2(-2.0f, -2.0f);
        float minw[TR_NT];
        #pragma unroll
        for (int j = 0; j < TR_NT; j++) minw[j] = INF;

        #pragma unroll 2
        for (int f = 0; f < FCH; f++) {
            const ulonglong2* fp = reinterpret_cast<const ulonglong2*>(sf + f * 8);
            ulonglong2 A = fp[0];   // tx2, ty2
            ulonglong2 B = fp[1];   // tz2, nf2

            float pm[4];
            #pragma unroll
            for (int jp = 0; jp < 4; jp++) {
                unsigned long long dot =
                    ffma2(tb2[jp][0], A.x, ffma2(tb2[jp][1], A.y, fmul2(tb2[jp][2], B.x)));
                // w = (nf - 2 dot) + nr = squared distance (>= 0)
                unsigned long long w2 = fadd2(ffma2(dot, M2, B.y), nr2[jp]);
                float wl, wh;
                unpk2(w2, wl, wh);
                minw[2*jp+0] = fminf(minw[2*jp+0], wl);
                minw[2*jp+1] = fminf(minw[2*jp+1], wh);
                pm[jp] = fminf(wl, wh);
            }
            float fv = fminf(fminf(pm[0], pm[1]), fminf(pm[2], pm[3]));
            // w >= 0 -> raw bits are order-preserving; reduce MIN directly
            unsigned ev = __reduce_min_sync(0xffffffffu, __float_as_uint(fv));
            if (lane == 0) s_fred[f][warp] = ev;
        }

        #pragma unroll
        for (int j = 0; j < TR_NT; j++)
            atomicMax(&g_ru[r0 + j], ~__float_as_uint(minw[j]));

        __syncthreads();
        if (tid < FCH) {
            const uint4* p = reinterpret_cast<const uint4*>(&s_fred[tid][0]);
            uint4 a = p[0], b = p[1];
            unsigned ev = umin(umin(umin(a.x, a.y), umin(a.z, a.w)),
                               umin(umin(b.x, b.y), umin(b.z, b.w)));
            atomicMax(&g_fv[fbase + tid], ~ev);
        }
    }
}

// ---------------- epilogue: 96KB read, sqrt/acos, fixed-order sum ----------------
// Grid is exactly (NRK+NFK)/NTH = 48 blocks; gid < NRK -> r item, else f item.
// Each thread consumes its scratch words and writes 0 back (re-arms replay).
__global__ __launch_bounds__(NTH, 4)
void epilogue_kernel(float* __restrict__ out) {
    const int tid = threadIdx.x;
    const int gid = blockIdx.x * NTH + tid;    // 0 .. NRK+NFK-1
    const int lane = tid & 31;
    const int warp = tid >> 5;

    float sAngR = 0.f, sSqR = 0.f, sAngF = 0.f, sSqF = 0.f;

    if (gid < NRK) {
        unsigned eu = g_ru[gid];
        unsigned et = g_rtr[gid];
        g_ru[gid] = 0u;
        g_rtr[gid] = 0u;
        float w = __uint_as_float(~eu);           // min squared distance
        sSqR = sqrtf(fmaxf(w, 0.0f) + EPS_CH);
        float trp = __uint_as_float(et);           // max trace + 1
        float cs = 0.5f * trp - 1.0f;
        cs = fminf(fmaxf(cs, -1.0f + EPS_ACOS), 1.0f - EPS_ACOS);
        sAngR = acosf(cs);
    } else {
        const int f = gid - NRK;
        unsigned ev = g_fv[f];
        unsigned et = g_ftr[f];
        g_fv[f] = 0u;
        g_ftr[f] = 0u;
        float w = __uint_as_float(~ev);
        sSqF = sqrtf(fmaxf(w, 0.0f) + EPS_CH);
        float trp = __uint_as_float(et);
        float cs = 0.5f * trp - 1.0f;
        cs = fminf(fmaxf(cs, -1.0f + EPS_ACOS), 1.0f - EPS_ACOS);
        sAngF = acosf(cs);
    }

    // fixed-tree block reduction (deterministic)
    #pragma unroll
    for (int off = 16; off; off >>= 1) {
        sAngR += __shfl_xor_sync(0xffffffffu, sAngR, off);
        sSqR  += __shfl_xor_sync(0xffffffffu, sSqR,  off);
        sAngF += __shfl_xor_sync(0xffffffffu, sAngF, off);
        sSqF  += __shfl_xor_sync(0xffffffffu, sSqF,  off);
    }
    __shared__ float s_buf[NTH/32][4];
    __shared__ int s_fin;
    if (lane == 0) {
        s_buf[warp][0] = sAngR; s_buf[warp][1] = sSqR;
        s_buf[warp][2] = sAngF; s_buf[warp][3] = sSqF;
    }
    __syncthreads();

    if (tid == 0) {
        float a0 = 0.f, a1 = 0.f, a2 = 0.f, a3 = 0.f;
        #pragma unroll
        for (int i = 0; i < NTH/32; i++) {
            a0 += s_buf[i][0]; a1 += s_buf[i][1]; a2 += s_buf[i][2]; a3 += s_buf[i][3];
        }
        g_psum[0][blockIdx.x] = a0;
        g_psum[1][blockIdx.x] = a1;
        g_psum[2][blockIdx.x] = a2;
        g_psum[3][blockIdx.x] = a3;
        __threadfence();
        unsigned old = atomicAdd(&g_done, 1u);
        s_fin = ((old % EBLK) == (EBLK - 1u));
    }
    __syncthreads();

    // finisher: lane-parallel fixed-tree combine of 48 partials (warp 0)
    if (s_fin && warp == 0) {
        __threadfence();                            // acquire all psum writes
        float c[4];
        #pragma unroll
        for (int comp = 0; comp < 4; comp++) {
            float s = (lane < EBLK) ? g_psum[comp][lane] : 0.f;
            if (lane < EBLK - 32) s += g_psum[comp][lane + 32];
            #pragma unroll
            for (int off = 16; off; off >>= 1)
                s += __shfl_xor_sync(0xffffffffu, s, off);
            c[comp] = s;
        }
        if (lane == 0) {
            float rloss = c[2] / (float)NFK + c[0] / (float)NRK;
            float tloss = c[1] / (float)NRK + c[3] / (float)NFK;
            out[0] = rloss + tloss * PI_F;
        }
    }
}

// ---------------- launch ----------------
extern "C" void kernel_launch(void* const* d_in, const int* in_sizes, int n_in,
                              void* d_out, int out_size) {
    const float* t_fake   = nullptr;  // 4096*3
    const float* R_fake   = nullptr;  // 4096*9
    const float* r_buffer = nullptr;  // 8192*9
    const float* t_buffer = nullptr;  // 8192*3
    for (int i = 0; i < n_in; i++) {
        switch (in_sizes[i]) {
            case NFK*3: t_fake   = (const float*)d_in[i]; break;
            case NFK*9: R_fake   = (const float*)d_in[i]; break;
            case NRK*9: r_buffer = (const float*)d_in[i]; break;
            case NRK*3: t_buffer = (const float*)d_in[i]; break;
            default: break;
        }
    }

    pair_kernel<<<GRID, NTH>>>(t_fake, R_fake, r_buffer, t_buffer);
    epilogue_kernel<<<EBLK, NTH>>>((float*)d_out);
}

// round 16
// speedup vs baseline: 1.7880x; 1.2295x over previous
#include <cuda_runtime.h>
#include <math.h>

// Problem constants (fixed shapes per reference)
#define NFK 4096
#define NRK 8192
#define NTH 256
#define FCH 64                  // f columns per tile
#define NCH (NFK/FCH)           // 64 f-chunks

// rot tiles: 256 threads, 4 r/thread -> 1024 r per tile
#define RT_NT 4
#define RT_RBLK (NTH*RT_NT)     // 1024
#define RT_NRB (NRK/RT_RBLK)    // 8
#define RT_TILES (NCH*RT_NRB)   // 512

// trans tiles: 256 threads, 8 r/thread -> 2048 r per tile
#define TR_NT 8
#define TR_RBLK (NTH*TR_NT)     // 2048
#define TR_NRB (NRK/TR_RBLK)    // 4
#define TR_TILES (NCH*TR_NRB)   // 256

#define GRID (RT_TILES + TR_TILES)   // 768

#define EBLK 48                 // epilogue blocks: 48*256 = NRK+NFK exactly
#define QBLK 48                 // quat blocks:     48*256 = NRK+NFK exactly

#define EPS_CH   1e-5f
#define EPS_ACOS 1e-6f
#define PI_F     3.14159265358979323846f

// ---------------- static device scratch (allocation-free) ----------------
// Encodings (reset value 0 = "no update"; epilogue re-zeros each replay):
//   g_ru[r]  = max of ~bits(min_f w)   -> w = squared translation distance >= 0
//   g_fv[f]  = max of ~bits(min_r w)
//   g_rtr[r] = max of  bits(max_f s)   -> s = (q_f . q_r)^2 in [0,1]; trace = 4s-1
//   g_ftr[f] = max of  bits(max_r s)
// Raw float bits of non-negative floats are order-preserving as uints.
__device__ unsigned g_done;            // finisher election counter (monotonic)
__device__ unsigned g_ru[NRK];
__device__ unsigned g_rtr[NRK];
__device__ unsigned g_fv[NFK];
__device__ unsigned g_ftr[NFK];
__device__ float    g_psum[4][EBLK];   // SoA per-epilogue-block partial sums
__device__ float4   g_qr[NRK];         // quaternions of r_buffer (recomputed per run)
__device__ float4   g_qf[NFK];         // quaternions of R_fake

// ---------------- packed f32x2 helpers ----------------
__device__ __forceinline__ unsigned long long pk2(float a, float b) {
    unsigned long long r;
    asm("mov.b64 %0, {%1, %2};" : "=l"(r) : "f"(a), "f"(b));
    return r;
}
__device__ __forceinline__ void unpk2(unsigned long long v, float& lo, float& hi) {
    asm("mov.b64 {%0, %1}, %2;" : "=f"(lo), "=f"(hi) : "l"(v));
}
__device__ __forceinline__ unsigned long long ffma2(unsigned long long a,
                                                    unsigned long long b,
                                                    unsigned long long c) {
    unsigned long long d;
    asm("fma.rn.f32x2 %0, %1, %2, %3;" : "=l"(d) : "l"(a), "l"(b), "l"(c));
    return d;
}
__device__ __forceinline__ unsigned long long fmul2(unsigned long long a,
                                                    unsigned long long b) {
    unsigned long long d;
    asm("mul.rn.f32x2 %0, %1, %2;" : "=l"(d) : "l"(a), "l"(b));
    return d;
}
__device__ __forceinline__ unsigned long long fadd2(unsigned long long a,
                                                    unsigned long long b) {
    unsigned long long d;
    asm("add.rn.f32x2 %0, %1, %2;" : "=l"(d) : "l"(a), "l"(b));
    return d;
}

// ---------------- prologue: rotation matrix -> unit quaternion ----------------
// Shepperd's branch method (stable), exact-normalized. Sign is irrelevant
// because only (q_f . q_r)^2 is consumed.
__global__ __launch_bounds__(NTH)
void quat_kernel(const float* __restrict__ R_fake,
                 const float* __restrict__ r_buffer) {
    const int i = blockIdx.x * NTH + threadIdx.x;    // 0 .. NRK+NFK-1
    const float* R;
    float4* dst;
    if (i < NRK) { R = r_buffer + (size_t)i * 9;        dst = &g_qr[i]; }
    else         { R = R_fake  + (size_t)(i - NRK) * 9; dst = &g_qf[i - NRK]; }

    float r00 = R[0], r01 = R[1], r02 = R[2];
    float r10 = R[3], r11 = R[4], r12 = R[5];
    float r20 = R[6], r21 = R[7], r22 = R[8];
    float t = r00 + r11 + r22;
    float w, x, y, z;
    if (t > 0.0f) {
        float S = sqrtf(1.0f + t) * 2.0f;
        w = 0.25f * S;
        x = (r21 - r12) / S;
        y = (r02 - r20) / S;
        z = (r10 - r01) / S;
    } else if (r00 > r11 && r00 > r22) {
        float S = sqrtf(1.0f + r00 - r11 - r22) * 2.0f;
        w = (r21 - r12) / S;
        x = 0.25f * S;
        y = (r01 + r10) / S;
        z = (r02 + r20) / S;
    } else if (r11 > r22) {
        float S = sqrtf(1.0f + r11 - r00 - r22) * 2.0f;
        w = (r02 - r20) / S;
        x = (r01 + r10) / S;
        y = 0.25f * S;
        z = (r12 + r21) / S;
    } else {
        float S = sqrtf(1.0f + r22 - r00 - r11) * 2.0f;
        w = (r10 - r01) / S;
        x = (r02 + r20) / S;
        y = (r12 + r21) / S;
        z = 0.25f * S;
    }
    float n = 1.0f / sqrtf(fmaf(w, w, fmaf(x, x, fmaf(y, y, z * z))));
    *dst = make_float4(w * n, x * n, y * n, z * n);
}

// ============ fused pair kernel: rot tiles then trans tiles ============
__global__ __launch_bounds__(NTH, 3)
void pair_kernel(const float* __restrict__ t_fake,
                 const float* __restrict__ t_buffer) {
    __shared__ __align__(16) float    sf[FCH * 8];       // 8 duplicated floats per f
    __shared__ __align__(16) unsigned s_fred[FCH][8];    // per-warp per-f results

    const int tid  = threadIdx.x;
    const int lane = tid & 31;
    const int warp = tid >> 5;

    if (blockIdx.x < RT_TILES) {
        // ========== rotation tile: s = (q_f . q_r)^2, 4-dim dot ==========
        const int bx = blockIdx.x;
        const int cx = bx & (NCH - 1);
        const int ry = bx >> 6;
        const int fbase = cx * FCH;
        const int rbase = ry * RT_RBLK;

        // stage duplicated quat tile: one thread per f
        if (tid < FCH) {
            float4 q = g_qf[fbase + tid];
            float* p = &sf[tid * 8];
            p[0] = q.x; p[1] = q.x; p[2] = q.y; p[3] = q.y;
            p[4] = q.z; p[5] = q.z; p[6] = q.w; p[7] = q.w;
        }

        const int r0 = rbase + tid * RT_NT;
        unsigned long long Qr2[2][4];
        #pragma unroll
        for (int jp = 0; jp < 2; jp++) {
            float4 qa = g_qr[r0 + 2 * jp];
            float4 qb = g_qr[r0 + 2 * jp + 1];
            Qr2[jp][0] = pk2(qa.x, qb.x);
            Qr2[jp][1] = pk2(qa.y, qb.y);
            Qr2[jp][2] = pk2(qa.z, qb.z);
            Qr2[jp][3] = pk2(qa.w, qb.w);
        }
        __syncthreads();

        const float INF = __int_as_float(0x7f800000);
        float maxs[RT_NT];
        #pragma unroll
        for (int j = 0; j < RT_NT; j++) maxs[j] = -INF;

        #pragma unroll 2
        for (int f = 0; f < FCH; f++) {
            const ulonglong2* fp = reinterpret_cast<const ulonglong2*>(sf + f * 8);
            ulonglong2 A = fp[0];   // qw2, qx2
            ulonglong2 B = fp[1];   // qy2, qz2

            float ft = -INF;
            #pragma unroll
            for (int jp = 0; jp < 2; jp++) {
                unsigned long long d =
                    ffma2(Qr2[jp][3], B.y,
                          ffma2(Qr2[jp][2], B.x,
                                ffma2(Qr2[jp][1], A.y, fmul2(Qr2[jp][0], A.x))));
                unsigned long long s2 = fmul2(d, d);   // s = d^2 >= 0
                float sl, sh;
                unpk2(s2, sl, sh);
                maxs[2*jp+0] = fmaxf(maxs[2*jp+0], sl);
                maxs[2*jp+1] = fmaxf(maxs[2*jp+1], sh);
                ft = fmaxf(ft, fmaxf(sl, sh));
            }
            // s >= 0 -> raw bits order-preserving
            unsigned et = __reduce_max_sync(0xffffffffu, __float_as_uint(ft));
            if (lane == 0) s_fred[f][warp] = et;
        }

        #pragma unroll
        for (int j = 0; j < RT_NT; j++)
            atomicMax(&g_rtr[r0 + j], __float_as_uint(maxs[j]));

        __syncthreads();
        if (tid < FCH) {
            const uint4* p = reinterpret_cast<const uint4*>(&s_fred[tid][0]);
            uint4 a = p[0], b = p[1];
            unsigned et = umax(umax(umax(a.x, a.y), umax(a.z, a.w)),
                               umax(umax(b.x, b.y), umax(b.z, b.w)));
            atomicMax(&g_ftr[fbase + tid], et);
        }
    } else {
        // ================= translation tile (unchanged from R14) =========
        const int bx = blockIdx.x - RT_TILES;
        const int cx = bx & (NCH - 1);
        const int ry = bx >> 6;
        const int fbase = cx * FCH;
        const int rbase = ry * TR_RBLK;

        if (tid < FCH) {
            int fg = fbase + tid;
            float tx = t_fake[fg*3+0], ty = t_fake[fg*3+1], tz = t_fake[fg*3+2];
            float nf = fmaf(tx, tx, fmaf(ty, ty, tz * tz));
            float* p = &sf[tid * 8];
            p[0] = tx; p[1] = tx; p[2] = ty; p[3] = ty;
            p[4] = tz; p[5] = tz; p[6] = nf; p[7] = nf;
        }

        const int r0 = rbase + tid * TR_NT;
        unsigned long long tb2[4][3], nr2[4];
        #pragma unroll
        for (int jp = 0; jp < 4; jp++) {
            int ra = r0 + 2 * jp, rb = ra + 1;
            float ax = t_buffer[ra*3+0], ay = t_buffer[ra*3+1], az = t_buffer[ra*3+2];
            float bx2 = t_buffer[rb*3+0], by = t_buffer[rb*3+1], bz = t_buffer[rb*3+2];
            tb2[jp][0] = pk2(ax, bx2);
            tb2[jp][1] = pk2(ay, by);
            tb2[jp][2] = pk2(az, bz);
            nr2[jp] = pk2(fmaf(ax, ax, fmaf(ay, ay, az * az)),
                          fmaf(bx2, bx2, fmaf(by, by, bz * bz)));
        }
        __syncthreads();

        const float INF = __int_as_float(0x7f800000);
        const unsigned long long M2 = pk2(-2.0f, -2.0f);
        float minw[TR_NT];
        #pragma unroll
        for (int j = 0; j < TR_NT; j++) minw[j] = INF;

        #pragma unroll 2
        for (int f = 0; f < FCH; f++) {
            const ulonglong2* fp = reinterpret_cast<const ulonglong2*>(sf + f * 8);
            ulonglong2 A = fp[0];   // tx2, ty2
            ulonglong2 B = fp[1];   // tz2, nf2

            float pm[4];
            #pragma unroll
            for (int jp = 0; jp < 4; jp++) {
                unsigned long long dot =
                    ffma2(tb2[jp][0], A.x, ffma2(tb2[jp][1], A.y, fmul2(tb2[jp][2], B.x)));
                unsigned long long w2 = fadd2(ffma2(dot, M2, B.y), nr2[jp]);
                float wl, wh;
                unpk2(w2, wl, wh);
                minw[2*jp+0] = fminf(minw[2*jp+0], wl);
                minw[2*jp+1] = fminf(minw[2*jp+1], wh);
                pm[jp] = fminf(wl, wh);
            }
            float fv = fminf(fminf(pm[0], pm[1]), fminf(pm[2], pm[3]));
            unsigned ev = __reduce_min_sync(0xffffffffu, __float_as_uint(fv));
            if (lane == 0) s_fred[f][warp] = ev;
        }

        #pragma unroll
        for (int j = 0; j < TR_NT; j++)
            atomicMax(&g_ru[r0 + j], ~__float_as_uint(minw[j]));

        __syncthreads();
        if (tid < FCH) {
            const uint4* p = reinterpret_cast<const uint4*>(&s_fred[tid][0]);
            uint4 a = p[0], b = p[1];
            unsigned ev = umin(umin(umin(a.x, a.y), umin(a.z, a.w)),
                               umin(umin(b.x, b.y), umin(b.z, b.w)));
            atomicMax(&g_fv[fbase + tid], ~ev);
        }
    }
}

// ---------------- epilogue: 96KB read, sqrt/acos, fixed-order sum ----------------
// Grid is exactly (NRK+NFK)/NTH = 48 blocks; gid < NRK -> r item, else f item.
// Each thread consumes its scratch words and writes 0 back (re-arms replay).
__global__ __launch_bounds__(NTH, 4)
void epilogue_kernel(float* __restrict__ out) {
    const int tid = threadIdx.x;
    const int gid = blockIdx.x * NTH + tid;    // 0 .. NRK+NFK-1
    const int lane = tid & 31;
    const int warp = tid >> 5;

    float sAngR = 0.f, sSqR = 0.f, sAngF = 0.f, sSqF = 0.f;

    if (gid < NRK) {
        unsigned eu = g_ru[gid];
        unsigned et = g_rtr[gid];
        g_ru[gid] = 0u;
        g_rtr[gid] = 0u;
        float w = __uint_as_float(~eu);            // min squared distance
        sSqR = sqrtf(fmaxf(w, 0.0f) + EPS_CH);
        float s = __uint_as_float(et);             // max (qf.qr)^2; trace = 4s-1
        float cs = fmaf(2.0f, s, -1.0f);           // 0.5*(trace-1) = 2s-1
        cs = fminf(fmaxf(cs, -1.0f + EPS_ACOS), 1.0f - EPS_ACOS);
        sAngR = acosf(cs);
    } else {
        const int f = gid - NRK;
        unsigned ev = g_fv[f];
        unsigned et = g_ftr[f];
        g_fv[f] = 0u;
        g_ftr[f] = 0u;
        float w = __uint_as_float(~ev);
        sSqF = sqrtf(fmaxf(w, 0.0f) + EPS_CH);
        float s = __uint_as_float(et);
        float cs = fmaf(2.0f, s, -1.0f);
        cs = fminf(fmaxf(cs, -1.0f + EPS_ACOS), 1.0f - EPS_ACOS);
        sAngF = acosf(cs);
    }

    // fixed-tree block reduction (deterministic)
    #pragma unroll
    for (int off = 16; off; off >>= 1) {
        sAngR += __shfl_xor_sync(0xffffffffu, sAngR, off);
        sSqR  += __shfl_xor_sync(0xffffffffu, sSqR,  off);
        sAngF += __shfl_xor_sync(0xffffffffu, sAngF, off);
        sSqF  += __shfl_xor_sync(0xffffffffu, sSqF,  off);
    }
    __shared__ float s_buf[NTH/32][4];
    __shared__ int s_fin;
    if (lane == 0) {
        s_buf[warp][0] = sAngR; s_buf[warp][1] = sSqR;
        s_buf[warp][2] = sAngF; s_buf[warp][3] = sSqF;
    }
    __syncthreads();

    if (tid == 0) {
        float a0 = 0.f, a1 = 0.f, a2 = 0.f, a3 = 0.f;
        #pragma unroll
        for (int i = 0; i < NTH/32; i++) {
            a0 += s_buf[i][0]; a1 += s_buf[i][1]; a2 += s_buf[i][2]; a3 += s_buf[i][3];
        }
        g_psum[0][blockIdx.x] = a0;
        g_psum[1][blockIdx.x] = a1;
        g_psum[2][blockIdx.x] = a2;
        g_psum[3][blockIdx.x] = a3;
        __threadfence();
        unsigned old = atomicAdd(&g_done, 1u);
        s_fin = ((old % EBLK) == (EBLK - 1u));
    }
    __syncthreads();

    // finisher: lane-parallel fixed-tree combine of 48 partials (warp 0)
    if (s_fin && warp == 0) {
        __threadfence();                            // acquire all psum writes
        float c[4];
        #pragma unroll
        for (int comp = 0; comp < 4; comp++) {
            float s = (lane < EBLK) ? g_psum[comp][lane] : 0.f;
            if (lane < EBLK - 32) s += g_psum[comp][lane + 32];
            #pragma unroll
            for (int off = 16; off; off >>= 1)
                s += __shfl_xor_sync(0xffffffffu, s, off);
            c[comp] = s;
        }
        if (lane == 0) {
            float rloss = c[2] / (float)NFK + c[0] / (float)NRK;
            float tloss = c[1] / (float)NRK + c[3] / (float)NFK;
            out[0] = rloss + tloss * PI_F;
        }
    }
}

// ---------------- launch ----------------
extern "C" void kernel_launch(void* const* d_in, const int* in_sizes, int n_in,
                              void* d_out, int out_size) {
    const float* t_fake   = nullptr;  // 4096*3
    const float* R_fake   = nullptr;  // 4096*9
    const float* r_buffer = nullptr;  // 8192*9
    const float* t_buffer = nullptr;  // 8192*3
    for (int i = 0; i < n_in; i++) {
        switch (in_sizes[i]) {
            case NFK*3: t_fake   = (const float*)d_in[i]; break;
            case NFK*9: R_fake   = (const float*)d_in[i]; break;
            case NRK*9: r_buffer = (const float*)d_in[i]; break;
            case NRK*3: t_buffer = (const float*)d_in[i]; break;
            default: break;
        }
    }

    quat_kernel<<<QBLK, NTH>>>(R_fake, r_buffer);
    pair_kernel<<<GRID, NTH>>>(t_fake, t_buffer);
    epilogue_kernel<<<EBLK, NTH>>>((float*)d_out);
}